// round 4
// baseline (speedup 1.0000x reference)
#include <cuda_runtime.h>

#define B_BATCH 64
#define NPTS    16384
#define SPLIT   2
#define PPB     (NPTS / SPLIT)     // 8192 points per block
#define TPTS    256                // points per tile
#define NTILE   (PPB / TPTS)       // 32
#define NBUF    3
#define KTAYLOR 12
#define NTRI    72                 // float2-pairs in upper triangle (incl. mirrored)

// partial triangle sums: [batch][split][144 floats]
__device__ float g_partial[B_BATCH * SPLIT * 144];

typedef unsigned long long ull;

__device__ __forceinline__ ull pack2(float a, float b) {
    ull r;
    asm("mov.b64 %0, {%1,%2};" : "=l"(r) : "f"(a), "f"(b));
    return r;
}
__device__ __forceinline__ void ffma2(ull& d, ull a, ull b) {
    asm("fma.rn.f32x2 %0, %1, %2, %0;" : "+l"(d) : "l"(a), "l"(b));
}
__device__ __forceinline__ void fadd2(ull& d, ull a) {
    asm("add.rn.f32x2 %0, %0, %1;" : "+l"(d) : "l"(a));
}
__device__ __forceinline__ unsigned smem_u32(const void* p) {
    unsigned a;
    asm("{ .reg .u64 t; cvta.to.shared.u64 t, %1; cvt.u32.u64 %0, t; }"
        : "=r"(a) : "l"(p));
    return a;
}
#define CP_ASYNC16(dst_u32, src_ptr) \
    asm volatile("cp.async.cg.shared.global [%0], [%1], 16;" \
                 :: "r"(dst_u32), "l"(src_ptr) : "memory")
#define CP_COMMIT() asm volatile("cp.async.commit_group;" ::: "memory")
#define CP_WAIT1()  asm volatile("cp.async.wait_group 1;" ::: "memory")

// triangle row start (in float2 slots): start[i] = sum_{r<i} (8 - r/2)
__device__ __host__ __forceinline__ constexpr int tri_start(int a) {
    return a == 0 ? 0 : 8 * a - ((a - 1) * (a - 1)) / 4;
}

// ---------------------------------------------------------------------------
// Kernel 1: symmetric second-moment. Coalesced cp.async loads into quad-
// transposed smem planes sh[buf][c][p] (plane c = features 4c..4c+3 of point
// p); conflict-free LDS.128 reads; 3-stage pipeline, 1 barrier/tile.
// Each thread handles point tid of each tile: 72 packed f32x2 FMAs/point.
// ---------------------------------------------------------------------------
__global__ __launch_bounds__(256, 1) void cov_kernel(const float* __restrict__ x) {
    __shared__ __align__(16) float4 sh[NBUF][4][TPTS];   // 48 KB

    const int tid  = threadIdx.x;
    const int w    = tid >> 5;
    const int lane = tid & 31;
    const int split = blockIdx.x, batch = blockIdx.y;

    const float4* __restrict__ gbase =
        (const float4*)(x + ((size_t)batch * NPTS + (size_t)split * PPB) * 16);
    // tile t occupies gbase + t*1024 .. +1024 float4s

    // this thread's 4 async destinations (c = tid&3 fixed, p = tid>>2 + 64k)
    unsigned dst[NBUF][4];
#pragma unroll
    for (int b = 0; b < NBUF; b++)
#pragma unroll
        for (int k = 0; k < 4; k++)
            dst[b][k] = smem_u32(&sh[b][tid & 3][(tid >> 2) + 64 * k]);

    ull acc[NTRI];
#pragma unroll
    for (int s = 0; s < NTRI; s++) acc[s] = 0ull;

#define ISSUE(t)                                                        \
    do {                                                                \
        if ((t) < NTILE) {                                              \
            const float4* src = gbase + (size_t)(t) * (TPTS * 4) + tid; \
            int bf = (t) % NBUF;                                        \
            CP_ASYNC16(dst[bf][0], src);                                \
            CP_ASYNC16(dst[bf][1], src + 256);                          \
            CP_ASYNC16(dst[bf][2], src + 512);                          \
            CP_ASYNC16(dst[bf][3], src + 768);                          \
        }                                                               \
        CP_COMMIT();                                                    \
    } while (0)

    ISSUE(0);
    ISSUE(1);

    for (int t = 0; t < NTILE; t++) {
        CP_WAIT1();          // my group for tile t complete
        __syncthreads();     // publish tile t; buf (t-1)%3 now free
        ISSUE(t + 2);

        const ulonglong2* pl = (const ulonglong2*)&sh[t % NBUF][0][0];
        ulonglong2 u0 = pl[tid];            // features 0-3
        ulonglong2 u1 = pl[TPTS + tid];     // features 4-7
        ulonglong2 u2 = pl[2 * TPTS + tid]; // features 8-11
        ulonglong2 u3 = pl[3 * TPTS + tid]; // features 12-15
        ull P[8] = {u0.x, u0.y, u1.x, u1.y, u2.x, u2.y, u3.x, u3.y};

#pragma unroll
        for (int i = 0; i < 16; i++) {
            unsigned u = (i & 1) ? (unsigned)(P[i >> 1] >> 32) : (unsigned)P[i >> 1];
            float xi = __uint_as_float(u);
            ull xi2 = pack2(xi, xi);
            const int s0 = tri_start(i) - (i >> 1);
#pragma unroll
            for (int c = (i >> 1); c < 8; c++) ffma2(acc[s0 + c], xi2, P[c]);
        }
    }
    __syncthreads();

    // warp reduce (5 butterfly rounds per slot)
#pragma unroll
    for (int s = 0; s < NTRI; s++) {
#pragma unroll
        for (int o = 16; o > 0; o >>= 1) {
            ull v = __shfl_xor_sync(0xffffffffu, acc[s], o);
            fadd2(acc[s], v);
        }
    }
    // cross-warp reduce via smem (alias tile buffers — all async done)
    float* red = (float*)sh;                 // need 8*144 floats
    if (lane == 0) {
        ull* rr = (ull*)red;
#pragma unroll
        for (int s = 0; s < NTRI; s++) rr[w * NTRI + s] = acc[s];
    }
    __syncthreads();
    if (tid < 144) {
        float v = 0.f;
#pragma unroll
        for (int ww = 0; ww < 8; ww++) v += red[ww * 144 + tid];
        g_partial[(batch * SPLIT + split) * 144 + tid] = v;
    }
}

// ---------------------------------------------------------------------------
// Kernel 2: per batch, 512 threads. Taylor logm on threads <256; FC with 16
// warps x 16 rows, half-warp per row (4-shfl reduce); L2-normalize.
// ---------------------------------------------------------------------------
__global__ __launch_bounds__(512) void post_kernel(const float* __restrict__ W,
                                                   const float* __restrict__ bias,
                                                   const float* __restrict__ pw,
                                                   float* __restrict__ out) {
    __shared__ __align__(16) float Em[256];
    __shared__ __align__(16) float Ab[2][256];
    __shared__ __align__(16) float fv[256];
    __shared__ __align__(16) float sout[256];
    __shared__ float rbuf[8];

    const int t = threadIdx.x;
    const int b = blockIdx.x;
    const int w = t >> 5, lane = t & 31;
    const int half = lane >> 4, hl = lane & 15;

    float e = 0.f;
    if (t < 256) {
        const int i = t >> 4, j = t & 15;
        const int a = i < j ? i : j;
        const int bb = i < j ? j : i;
        const int fidx = 2 * (tri_start(a) + (bb >> 1) - (a >> 1)) + (bb & 1);
        float s0 = g_partial[(b * SPLIT + 0) * 144 + fidx]
                 + g_partial[(b * SPLIT + 1) * 144 + fidx];
        e = s0 * (1.0f / (float)NPTS) - (i == j ? 1.0f : 0.0f);
        Em[t] = e;
        Ab[0][t] = e;
    }
    __syncthreads();

    float ec[16];
    {
        const int j = t & 15;
#pragma unroll
        for (int m = 0; m < 16; m++) ec[m] = Em[m * 16 + j];
    }

    float S = e;   // k=1 term
    int cur = 0;
#pragma unroll
    for (int k = 2; k <= KTAYLOR; k++) {
        if (t < 256) {
            const int i = t >> 4;
            const float4* arow = (const float4*)(Ab[cur] + i * 16);
            float4 a0 = arow[0], a1 = arow[1], a2 = arow[2], a3 = arow[3];
            float acc = a0.x * ec[0] + a0.y * ec[1] + a0.z * ec[2] + a0.w * ec[3]
                      + a1.x * ec[4] + a1.y * ec[5] + a1.z * ec[6] + a1.w * ec[7]
                      + a2.x * ec[8] + a2.y * ec[9] + a2.z * ec[10] + a2.w * ec[11]
                      + a3.x * ec[12] + a3.y * ec[13] + a3.z * ec[14] + a3.w * ec[15];
            S += (((k & 1) ? 1.0f : -1.0f) / (float)k) * acc;
            Ab[cur ^ 1][t] = acc;
        }
        cur ^= 1;
        __syncthreads();
    }

    if (t < 256) {
        float pe = pw[0];
        float av = fabsf(S);
        fv[t] = (av > 0.0f) ? copysignf(powf(av, pe), S) : 0.0f;
    }
    __syncthreads();

    // FC: warp w handles rows [16w, 16w+16); half-warp per row.
    // Lane's fv chunk: 16 floats at hl*16, held in registers.
    const float4* fvv = (const float4*)fv;
    float4 f0 = fvv[hl * 4], f1 = fvv[hl * 4 + 1],
           f2 = fvv[hl * 4 + 2], f3 = fvv[hl * 4 + 3];

#pragma unroll 4
    for (int it = 0; it < 8; it++) {
        int row = w * 16 + it * 2 + half;
        const float4* wr = (const float4*)(W + (size_t)row * 256 + hl * 16);
        float4 w0 = wr[0], w1 = wr[1], w2 = wr[2], w3 = wr[3];
        float pa = w0.x * f0.x + w0.y * f0.y + w0.z * f0.z + w0.w * f0.w
                 + w1.x * f1.x + w1.y * f1.y + w1.z * f1.z + w1.w * f1.w;
        float pb = w2.x * f2.x + w2.y * f2.y + w2.z * f2.z + w2.w * f2.w
                 + w3.x * f3.x + w3.y * f3.y + w3.z * f3.z + w3.w * f3.w;
        float pp = pa + pb;
#pragma unroll
        for (int o = 8; o > 0; o >>= 1) pp += __shfl_xor_sync(0xffffffffu, pp, o);
        if (hl == 0) sout[row] = pp + bias[row];
    }
    __syncthreads();

    // L2 normalize across the 256 outputs of this batch
    if (t < 256) {
        float v = sout[t];
        float sq = v * v;
#pragma unroll
        for (int o = 16; o > 0; o >>= 1) sq += __shfl_xor_sync(0xffffffffu, sq, o);
        if (lane == 0) rbuf[w] = sq;
    }
    __syncthreads();
    if (t < 256) {
        float tot = rbuf[0] + rbuf[1] + rbuf[2] + rbuf[3] +
                    rbuf[4] + rbuf[5] + rbuf[6] + rbuf[7];
        float nrm = fmaxf(sqrtf(tot), 1e-12f);
        out[b * 256 + t] = sout[t] / nrm;
    }
}

extern "C" void kernel_launch(void* const* d_in, const int* in_sizes, int n_in,
                              void* d_out, int out_size) {
    const float* x = (const float*)d_in[0];
    const float* W = (const float*)d_in[1];
    const float* b = (const float*)d_in[2];
    const float* p = (const float*)d_in[3];
    float* out = (float*)d_out;

    cov_kernel<<<dim3(SPLIT, B_BATCH), 256>>>(x);
    post_kernel<<<B_BATCH, 512>>>(W, b, p, out);
}

// round 6
// speedup vs baseline: 1.0661x; 1.0661x over previous
#include <cuda_runtime.h>

#define B_BATCH 64
#define NPTS    16384
#define SPLIT   2
#define PPB     (NPTS / SPLIT)     // 8192 points per block
#define WPTS    1024               // points per warp
#define ITERS   32                 // 32 points per warp-iter
#define DEPTH   3
#define KTAYLOR 8
#define NTRI    72                 // float2-pairs in upper triangle (incl. mirrored)

// partial triangle sums: [batch][split][144 floats]
__device__ float g_partial[B_BATCH * SPLIT * 144];

typedef unsigned long long ull;

__device__ __forceinline__ ull pack2(float a, float b) {
    ull r;
    asm("mov.b64 %0, {%1,%2};" : "=l"(r) : "f"(a), "f"(b));
    return r;
}
__device__ __forceinline__ void ffma2(ull& d, ull a, ull b) {
    asm("fma.rn.f32x2 %0, %1, %2, %0;" : "+l"(d) : "l"(a), "l"(b));
}
__device__ __forceinline__ void fadd2(ull& d, ull a) {
    asm("add.rn.f32x2 %0, %0, %1;" : "+l"(d) : "l"(a));
}
__device__ __forceinline__ unsigned smem_u32(const void* p) {
    unsigned a;
    asm("{ .reg .u64 t; cvta.to.shared.u64 t, %1; cvt.u32.u64 %0, t; }"
        : "=r"(a) : "l"(p));
    return a;
}
#define CP_ASYNC16(dst_u32, src_ptr) \
    asm volatile("cp.async.cg.shared.global [%0], [%1], 16;" \
                 :: "r"(dst_u32), "l"(src_ptr) : "memory")
#define CP_COMMIT() asm volatile("cp.async.commit_group;" ::: "memory")
#define CP_WAIT(n)  asm volatile("cp.async.wait_group %0;" :: "n"(n) : "memory")

// triangle row start (in float2 slots): start[i] = sum_{r<i} (8 - r/2)
__device__ __host__ __forceinline__ constexpr int tri_start(int a) {
    return a == 0 ? 0 : 8 * a - ((a - 1) * (a - 1)) / 4;
}

// ---------------------------------------------------------------------------
// Kernel 1: symmetric second-moment, WARP-PRIVATE cp.async pipeline.
// Warp w owns points [w*1024, (w+1)*1024) of the block's 8192, and a private
// 3-deep ring of 2KB tile buffers (transposed planes, XOR-swizzled so both
// the STS side (via cp.async) and the LDS side are bank-conflict-free).
// No __syncthreads in the main loop — only per-warp wait_group/syncwarp.
// Per 32-point iter: 4 cp.async (coalesced, nL=4) + 4 LDS.128 + 72 f32x2 FMA.
// ---------------------------------------------------------------------------
__global__ __launch_bounds__(256, 1) void cov_kernel(const float* __restrict__ x) {
    // [warp][buf][plane q][slot] : plane q holds features 4q..4q+3 of 32 points
    __shared__ __align__(16) float4 sbuf[8][DEPTH][4][32];   // 48 KB exactly

    const int tid  = threadIdx.x;
    const int w    = tid >> 5;
    const int lane = tid & 31;
    const int split = blockIdx.x, batch = blockIdx.y;

    const float4* __restrict__ gw =
        (const float4*)x + ((size_t)batch * NPTS + (size_t)split * PPB + w * WPTS) * 4;
    // iter i chunk: gw + i*128 (+ k*32 + lane), k = 0..3

    // cp.async destinations: load k gives lane the float4 of point 8k+(lane>>2),
    // quarter q = lane&3. Swizzled slot = p ^ (2q) -> conflict-free phases.
    const int q = lane & 3;
    const int dq = lane >> 2;
    unsigned dst[DEPTH][4];
#pragma unroll
    for (int b = 0; b < DEPTH; b++)
#pragma unroll
        for (int k = 0; k < 4; k++)
            dst[b][k] = smem_u32(&sbuf[w][b][q][(8 * k + dq) ^ (2 * q)]);

    // LDS sources: lane reads its own point p_local = lane, quarter qq at
    // slot lane ^ (2*qq)
    unsigned src_s[DEPTH][4];
#pragma unroll
    for (int b = 0; b < DEPTH; b++)
#pragma unroll
        for (int qq = 0; qq < 4; qq++)
            src_s[b][qq] = smem_u32(&sbuf[w][b][qq][lane ^ (2 * qq)]);

    ull acc[NTRI];
#pragma unroll
    for (int s = 0; s < NTRI; s++) acc[s] = 0ull;

#define ISSUE(i)                                                   \
    do {                                                           \
        if ((i) < ITERS) {                                         \
            const float4* sp = gw + (size_t)(i) * 128 + lane;      \
            int bf = (i) % DEPTH;                                  \
            CP_ASYNC16(dst[bf][0], sp);                            \
            CP_ASYNC16(dst[bf][1], sp + 32);                       \
            CP_ASYNC16(dst[bf][2], sp + 64);                       \
            CP_ASYNC16(dst[bf][3], sp + 96);                       \
        }                                                          \
        CP_COMMIT();                                               \
    } while (0)

    ISSUE(0); ISSUE(1); ISSUE(2);

    for (int i = 0; i < ITERS; i++) {
        CP_WAIT(2);          // group i complete (i+1, i+2 still pending)
        __syncwarp();

        const int bf = i % DEPTH;
        ulonglong2 u0, u1, u2, u3;
        asm volatile("ld.shared.v2.u64 {%0,%1}, [%2];" : "=l"(u0.x), "=l"(u0.y) : "r"(src_s[bf][0]));
        asm volatile("ld.shared.v2.u64 {%0,%1}, [%2];" : "=l"(u1.x), "=l"(u1.y) : "r"(src_s[bf][1]));
        asm volatile("ld.shared.v2.u64 {%0,%1}, [%2];" : "=l"(u2.x), "=l"(u2.y) : "r"(src_s[bf][2]));
        asm volatile("ld.shared.v2.u64 {%0,%1}, [%2];" : "=l"(u3.x), "=l"(u3.y) : "r"(src_s[bf][3]));

        __syncwarp();
        ISSUE(i + 3);        // refills buf (i+3)%3 == bf; reads above already done

        ull P[8] = {u0.x, u0.y, u1.x, u1.y, u2.x, u2.y, u3.x, u3.y};
#pragma unroll
        for (int fi = 0; fi < 16; fi++) {
            unsigned u = (fi & 1) ? (unsigned)(P[fi >> 1] >> 32) : (unsigned)P[fi >> 1];
            float xi = __uint_as_float(u);
            ull xi2 = pack2(xi, xi);
            const int s0 = tri_start(fi) - (fi >> 1);
#pragma unroll
            for (int c = (fi >> 1); c < 8; c++) ffma2(acc[s0 + c], xi2, P[c]);
        }
    }
    CP_WAIT(0);
    __syncthreads();

    // warp reduce (5 butterfly rounds per slot)
#pragma unroll
    for (int s = 0; s < NTRI; s++) {
#pragma unroll
        for (int o = 16; o > 0; o >>= 1) {
            ull v = __shfl_xor_sync(0xffffffffu, acc[s], o);
            fadd2(acc[s], v);
        }
    }
    // cross-warp reduce via smem (alias tile buffers — all async traffic done)
    float* red = (float*)sbuf;               // need 8*144 floats
    if (lane == 0) {
        ull* rr = (ull*)red;
#pragma unroll
        for (int s = 0; s < NTRI; s++) rr[w * NTRI + s] = acc[s];
    }
    __syncthreads();
    if (tid < 144) {
        float v = 0.f;
#pragma unroll
        for (int ww = 0; ww < 8; ww++) v += red[ww * 144 + tid];
        g_partial[(batch * SPLIT + split) * 144 + tid] = v;
    }
#undef ISSUE
}

// ---------------------------------------------------------------------------
// Kernel 2: per batch, 512 threads. Taylor logm (8 terms) on threads <256;
// tree-reduced dot; __powf; FC with 16 warps x 16 rows (half-warp per row);
// L2-normalize.
// ---------------------------------------------------------------------------
__global__ __launch_bounds__(512) void post_kernel(const float* __restrict__ W,
                                                   const float* __restrict__ bias,
                                                   const float* __restrict__ pw,
                                                   float* __restrict__ out) {
    __shared__ __align__(16) float Em[256];
    __shared__ __align__(16) float Ab[2][256];
    __shared__ __align__(16) float fv[256];
    __shared__ __align__(16) float sout[256];
    __shared__ float rbuf[8];

    const int t = threadIdx.x;
    const int b = blockIdx.x;
    const int w = t >> 5, lane = t & 31;
    const int half = lane >> 4, hl = lane & 15;

    float e = 0.f;
    if (t < 256) {
        const int i = t >> 4, j = t & 15;
        const int a = i < j ? i : j;
        const int bb = i < j ? j : i;
        const int fidx = 2 * (tri_start(a) + (bb >> 1) - (a >> 1)) + (bb & 1);
        float s0 = g_partial[(b * SPLIT + 0) * 144 + fidx]
                 + g_partial[(b * SPLIT + 1) * 144 + fidx];
        e = s0 * (1.0f / (float)NPTS) - (i == j ? 1.0f : 0.0f);
        Em[t] = e;
        Ab[0][t] = e;
    }
    __syncthreads();

    float ec[16];
    {
        const int j = t & 15;
#pragma unroll
        for (int m = 0; m < 16; m++) ec[m] = Em[m * 16 + j];
    }

    float S = e;   // k=1 term
    int cur = 0;
#pragma unroll
    for (int k = 2; k <= KTAYLOR; k++) {
        if (t < 256) {
            const int i = t >> 4;
            const float4* arow = (const float4*)(Ab[cur] + i * 16);
            float4 a0 = arow[0], a1 = arow[1], a2 = arow[2], a3 = arow[3];
            float p0 = a0.x * ec[0]  + a0.y * ec[1]  + a0.z * ec[2]  + a0.w * ec[3];
            float p1 = a1.x * ec[4]  + a1.y * ec[5]  + a1.z * ec[6]  + a1.w * ec[7];
            float p2 = a2.x * ec[8]  + a2.y * ec[9]  + a2.z * ec[10] + a2.w * ec[11];
            float p3 = a3.x * ec[12] + a3.y * ec[13] + a3.z * ec[14] + a3.w * ec[15];
            float acc = (p0 + p1) + (p2 + p3);
            S += (((k & 1) ? 1.0f : -1.0f) / (float)k) * acc;
            Ab[cur ^ 1][t] = acc;
        }
        cur ^= 1;
        __syncthreads();
    }

    if (t < 256) {
        float pe = pw[0];
        float av = fabsf(S);
        fv[t] = (av > 0.0f) ? copysignf(__powf(av, pe), S) : 0.0f;
    }
    __syncthreads();

    // FC: warp w handles rows [16w, 16w+16); half-warp per row.
    const float4* fvv = (const float4*)fv;
    float4 f0 = fvv[hl * 4], f1 = fvv[hl * 4 + 1],
           f2 = fvv[hl * 4 + 2], f3 = fvv[hl * 4 + 3];

#pragma unroll 4
    for (int it = 0; it < 8; it++) {
        int row = w * 16 + it * 2 + half;
        const float4* wr = (const float4*)(W + (size_t)row * 256 + hl * 16);
        float4 w0 = wr[0], w1 = wr[1], w2 = wr[2], w3 = wr[3];
        float pa = w0.x * f0.x + w0.y * f0.y + w0.z * f0.z + w0.w * f0.w
                 + w1.x * f1.x + w1.y * f1.y + w1.z * f1.z + w1.w * f1.w;
        float pb = w2.x * f2.x + w2.y * f2.y + w2.z * f2.z + w2.w * f2.w
                 + w3.x * f3.x + w3.y * f3.y + w3.z * f3.z + w3.w * f3.w;
        float pp = pa + pb;
#pragma unroll
        for (int o = 8; o > 0; o >>= 1) pp += __shfl_xor_sync(0xffffffffu, pp, o);
        if (hl == 0) sout[row] = pp + bias[row];
    }
    __syncthreads();

    // L2 normalize across the 256 outputs of this batch
    if (t < 256) {
        float v = sout[t];
        float sq = v * v;
#pragma unroll
        for (int o = 16; o > 0; o >>= 1) sq += __shfl_xor_sync(0xffffffffu, sq, o);
        if (lane == 0) rbuf[w] = sq;
    }
    __syncthreads();
    if (t < 256) {
        float tot = rbuf[0] + rbuf[1] + rbuf[2] + rbuf[3] +
                    rbuf[4] + rbuf[5] + rbuf[6] + rbuf[7];
        float nrm = fmaxf(sqrtf(tot), 1e-12f);
        out[b * 256 + t] = sout[t] / nrm;
    }
}

extern "C" void kernel_launch(void* const* d_in, const int* in_sizes, int n_in,
                              void* d_out, int out_size) {
    const float* x = (const float*)d_in[0];
    const float* W = (const float*)d_in[1];
    const float* b = (const float*)d_in[2];
    const float* p = (const float*)d_in[3];
    float* out = (float*)d_out;

    cov_kernel<<<dim3(SPLIT, B_BATCH), 256>>>(x);
    post_kernel<<<B_BATCH, 512>>>(W, b, p, out);
}